// round 2
// baseline (speedup 1.0000x reference)
#include <cuda_runtime.h>
#include <cstdint>

// Problem constants
#define BB      8192
#define DIN     64
#define DMID    1024
#define DOUT    64
#define KDOM    4

// Tiling
#define TM      128
#define TN      128
#define TK      16
#define PADDED  (BB + KDOM * TM)      // 8704: per-domain segments padded to TM
#define MTILES  (PADDED / TM)         // 68
#define NTILES  (DMID / TN)           // 8

// Scratch (device globals: no allocation allowed)
__device__ float g_bufA[PADDED * DMID];
__device__ float g_bufB[PADDED * DMID];
__device__ int   g_perm[PADDED];      // padded slot -> source row (-1 = padding)
__device__ int   g_seg[KDOM + 1];     // padded segment starts per domain
__device__ int   g_cnt[KDOM];

// ---------------------------------------------------------------------------
// Setup: histogram domains, compute tile-aligned segment offsets, init perm
// NOTE: domains is int32 on device (JAX x32 default downcasts the int64).
// ---------------------------------------------------------------------------
__global__ void setup_kernel(const int* __restrict__ domains) {
    __shared__ int cnt[KDOM];
    int t = threadIdx.x;
    if (t < KDOM) cnt[t] = 0;
    __syncthreads();
    for (int i = t; i < BB; i += blockDim.x) {
        int d = domains[i] & (KDOM - 1);   // clamp defensively
        atomicAdd(&cnt[d], 1);
    }
    for (int i = t; i < PADDED; i += blockDim.x)
        g_perm[i] = -1;
    __syncthreads();
    if (t == 0) {
        int off = 0;
        for (int d = 0; d < KDOM; d++) {
            g_seg[d] = off;
            g_cnt[d] = 0;
            off += (cnt[d] + TM - 1) / TM * TM;
        }
        g_seg[KDOM] = off;
    }
}

__global__ void build_perm_kernel(const int* __restrict__ domains) {
    int i = blockIdx.x * blockDim.x + threadIdx.x;
    if (i < BB) {
        int d = domains[i] & (KDOM - 1);
        int pos = g_seg[d] + atomicAdd(&g_cnt[d], 1);
        if (pos >= 0 && pos < PADDED)
            g_perm[pos] = i;
    }
}

// ---------------------------------------------------------------------------
// Main fused GEMM: C[TM x TN] = act(A[TM x Kdim] @ W[Kdim x DMID] + bias)
// GATHER=true: A rows come from X via g_perm (layer 1).
// Per-tile domain selects branch weights via wstride/bstride (0 => shared).
// ---------------------------------------------------------------------------
template<bool GATHER>
__global__ __launch_bounds__(256, 2)
void gemm128_kernel(const float* __restrict__ Xin, int a_sel,
                    const float* __restrict__ Wbase,
                    const float* __restrict__ bbase,
                    int c_sel, int Kdim,
                    long wstride, int bstride, int do_relu)
{
    __shared__ __align__(16) float As[2][TK][TM];
    __shared__ __align__(16) float Bs[2][TK][TN];

    const int m0  = blockIdx.y * TM;
    const int n0  = blockIdx.x * TN;
    const int tid = threadIdx.x;

    int dom = 0;
#pragma unroll
    for (int d = 1; d < KDOM; d++) if (m0 >= g_seg[d]) dom = d;
    const float* W    = Wbase + (long)dom * wstride;
    const float* bias = bbase + (long)dom * bstride;

    // A-tile loaders: 128 rows x 16 k, stored transposed [k][m]
    const int arow = tid & 127;
    const int akq  = tid >> 7;            // loads k-quads akq and akq+2
    // B-tile loaders: 16 k x 128 n
    const int brow = tid >> 5;            // rows brow, brow+8
    const int bn4  = tid & 31;            // float4 index in row

    const float* Arow;
    bool avalid = true;
    if (GATHER) {
        int s = g_perm[m0 + arow];
        avalid = (s >= 0);
        Arow = Xin + (long)(avalid ? s : 0) * Kdim;
    } else {
        const float* A = a_sel ? g_bufB : g_bufA;
        Arow = A + (long)(m0 + arow) * Kdim;
    }

    const int tx = tid & 15;
    const int ty = tid >> 4;

    float acc[8][8];
#pragma unroll
    for (int i = 0; i < 8; i++)
#pragma unroll
        for (int j = 0; j < 8; j++) acc[i][j] = 0.f;

    const int nkt = Kdim / TK;
    float4 apre[2], bpre[2];

    // preload k-tile 0
#pragma unroll
    for (int i = 0; i < 2; i++) {
        int kk = (akq + 2 * i) * 4;
        apre[i] = avalid ? *(const float4*)(Arow + kk) : make_float4(0.f, 0.f, 0.f, 0.f);
        int kr = brow + 8 * i;
        bpre[i] = *(const float4*)(W + (long)kr * DMID + n0 + bn4 * 4);
    }
#pragma unroll
    for (int i = 0; i < 2; i++) {
        int kk = (akq + 2 * i) * 4;
        As[0][kk + 0][arow] = apre[i].x;
        As[0][kk + 1][arow] = apre[i].y;
        As[0][kk + 2][arow] = apre[i].z;
        As[0][kk + 3][arow] = apre[i].w;
        *(((float4*)Bs[0][brow + 8 * i]) + bn4) = bpre[i];
    }
    __syncthreads();

    int buf = 0;
    for (int kt = 0; kt < nkt; kt++) {
        if (kt + 1 < nkt) {
            int kb = (kt + 1) * TK;
#pragma unroll
            for (int i = 0; i < 2; i++) {
                int kk = (akq + 2 * i) * 4;
                apre[i] = avalid ? *(const float4*)(Arow + kb + kk)
                                 : make_float4(0.f, 0.f, 0.f, 0.f);
                int kr = brow + 8 * i;
                bpre[i] = *(const float4*)(W + (long)(kb + kr) * DMID + n0 + bn4 * 4);
            }
        }
        // compute on buf
#pragma unroll
        for (int k = 0; k < TK; k++) {
            float4 a0 = *(const float4*)&As[buf][k][ty * 4];
            float4 a1 = *(const float4*)&As[buf][k][64 + ty * 4];
            float4 b0 = *(const float4*)&Bs[buf][k][tx * 4];
            float4 b1 = *(const float4*)&Bs[buf][k][64 + tx * 4];
            float a[8] = {a0.x, a0.y, a0.z, a0.w, a1.x, a1.y, a1.z, a1.w};
            float b[8] = {b0.x, b0.y, b0.z, b0.w, b1.x, b1.y, b1.z, b1.w};
#pragma unroll
            for (int i = 0; i < 8; i++)
#pragma unroll
                for (int j = 0; j < 8; j++)
                    acc[i][j] = fmaf(a[i], b[j], acc[i][j]);
        }
        if (kt + 1 < nkt) {
            int nb = buf ^ 1;
#pragma unroll
            for (int i = 0; i < 2; i++) {
                int kk = (akq + 2 * i) * 4;
                As[nb][kk + 0][arow] = apre[i].x;
                As[nb][kk + 1][arow] = apre[i].y;
                As[nb][kk + 2][arow] = apre[i].z;
                As[nb][kk + 3][arow] = apre[i].w;
                *(((float4*)Bs[nb][brow + 8 * i]) + bn4) = bpre[i];
            }
        }
        __syncthreads();
        buf ^= 1;
    }

    // epilogue: bias + optional ReLU
    float4 bias0 = *(const float4*)(bias + n0 + tx * 4);
    float4 bias1 = *(const float4*)(bias + n0 + 64 + tx * 4);
    float* Cb = c_sel ? g_bufB : g_bufA;
#pragma unroll
    for (int i = 0; i < 8; i++) {
        int row = m0 + ((i < 4) ? (ty * 4 + i) : (64 + ty * 4 + i - 4));
        float4 v0 = make_float4(acc[i][0] + bias0.x, acc[i][1] + bias0.y,
                                acc[i][2] + bias0.z, acc[i][3] + bias0.w);
        float4 v1 = make_float4(acc[i][4] + bias1.x, acc[i][5] + bias1.y,
                                acc[i][6] + bias1.z, acc[i][7] + bias1.w);
        if (do_relu) {
            v0.x = fmaxf(v0.x, 0.f); v0.y = fmaxf(v0.y, 0.f);
            v0.z = fmaxf(v0.z, 0.f); v0.w = fmaxf(v0.w, 0.f);
            v1.x = fmaxf(v1.x, 0.f); v1.y = fmaxf(v1.y, 0.f);
            v1.z = fmaxf(v1.z, 0.f); v1.w = fmaxf(v1.w, 0.f);
        }
        *(float4*)(Cb + (long)row * DMID + n0 + tx * 4) = v0;
        *(float4*)(Cb + (long)row * DMID + n0 + 64 + tx * 4) = v1;
    }
}

// ---------------------------------------------------------------------------
// Last layer: [TM x 1024] @ BW4[dom][1024 x 64] + Bb4[dom], scatter to output
// ---------------------------------------------------------------------------
__global__ __launch_bounds__(256, 2)
void gemm_last_kernel(int a_sel, const float* __restrict__ Wbase,
                      const float* __restrict__ bbase, float* __restrict__ out)
{
    __shared__ __align__(16) float As[2][TK][TM];
    __shared__ __align__(16) float Bs[2][TK][DOUT];

    const int m0  = blockIdx.x * TM;
    const int tid = threadIdx.x;

    int dom = 0;
#pragma unroll
    for (int d = 1; d < KDOM; d++) if (m0 >= g_seg[d]) dom = d;
    const float* W    = Wbase + (long)dom * (DMID * DOUT);
    const float* bias = bbase + (long)dom * DOUT;
    const float* A = a_sel ? g_bufB : g_bufA;

    const int arow = tid & 127;
    const int akq  = tid >> 7;
    const int bkr  = tid >> 4;   // 0..15 (k row)
    const int bn4  = tid & 15;   // float4 in row of 64
    const int tx   = tid & 15;
    const int ty   = tid >> 4;

    const float* Arow = A + (long)(m0 + arow) * DMID;

    float acc[8][4];
#pragma unroll
    for (int i = 0; i < 8; i++)
#pragma unroll
        for (int j = 0; j < 4; j++) acc[i][j] = 0.f;

    const int nkt = DMID / TK;   // 64
    float4 apre[2], bpre;

#pragma unroll
    for (int i = 0; i < 2; i++) {
        int kk = (akq + 2 * i) * 4;
        apre[i] = *(const float4*)(Arow + kk);
    }
    bpre = *(const float4*)(W + (long)bkr * DOUT + bn4 * 4);
#pragma unroll
    for (int i = 0; i < 2; i++) {
        int kk = (akq + 2 * i) * 4;
        As[0][kk + 0][arow] = apre[i].x;
        As[0][kk + 1][arow] = apre[i].y;
        As[0][kk + 2][arow] = apre[i].z;
        As[0][kk + 3][arow] = apre[i].w;
    }
    *(((float4*)Bs[0][bkr]) + bn4) = bpre;
    __syncthreads();

    int buf = 0;
    for (int kt = 0; kt < nkt; kt++) {
        if (kt + 1 < nkt) {
            int kb = (kt + 1) * TK;
#pragma unroll
            for (int i = 0; i < 2; i++) {
                int kk = (akq + 2 * i) * 4;
                apre[i] = *(const float4*)(Arow + kb + kk);
            }
            bpre = *(const float4*)(W + (long)(kb + bkr) * DOUT + bn4 * 4);
        }
#pragma unroll
        for (int k = 0; k < TK; k++) {
            float4 a0 = *(const float4*)&As[buf][k][ty * 4];
            float4 a1 = *(const float4*)&As[buf][k][64 + ty * 4];
            float4 b0 = *(const float4*)&Bs[buf][k][tx * 4];
            float a[8] = {a0.x, a0.y, a0.z, a0.w, a1.x, a1.y, a1.z, a1.w};
            float b[4] = {b0.x, b0.y, b0.z, b0.w};
#pragma unroll
            for (int i = 0; i < 8; i++)
#pragma unroll
                for (int j = 0; j < 4; j++)
                    acc[i][j] = fmaf(a[i], b[j], acc[i][j]);
        }
        if (kt + 1 < nkt) {
            int nb = buf ^ 1;
#pragma unroll
            for (int i = 0; i < 2; i++) {
                int kk = (akq + 2 * i) * 4;
                As[nb][kk + 0][arow] = apre[i].x;
                As[nb][kk + 1][arow] = apre[i].y;
                As[nb][kk + 2][arow] = apre[i].z;
                As[nb][kk + 3][arow] = apre[i].w;
            }
            *(((float4*)Bs[nb][bkr]) + bn4) = bpre;
        }
        __syncthreads();
        buf ^= 1;
    }

    // epilogue: bias (no relu), scatter back to original row order
    float4 bias0 = *(const float4*)(bias + tx * 4);
#pragma unroll
    for (int i = 0; i < 8; i++) {
        int row = m0 + ((i < 4) ? (ty * 4 + i) : (64 + ty * 4 + i - 4));
        int src = g_perm[row];
        if (src >= 0) {
            float4 v = make_float4(acc[i][0] + bias0.x, acc[i][1] + bias0.y,
                                   acc[i][2] + bias0.z, acc[i][3] + bias0.w);
            *(float4*)(out + (long)src * DOUT + tx * 4) = v;
        }
    }
}

// ---------------------------------------------------------------------------
extern "C" void kernel_launch(void* const* d_in, const int* in_sizes, int n_in,
                              void* d_out, int out_size)
{
    const float* X   = (const float*)d_in[0];
    const int*   dom = (const int*)d_in[1];      // int32 (JAX x32 default)
    const float *W1 = (const float*)d_in[2],  *b1  = (const float*)d_in[3];
    const float *W2 = (const float*)d_in[4],  *b2  = (const float*)d_in[5];
    const float *W3 = (const float*)d_in[6],  *b3  = (const float*)d_in[7];
    const float *W4 = (const float*)d_in[8],  *b4  = (const float*)d_in[9];
    const float *BW1 = (const float*)d_in[10], *Bb1 = (const float*)d_in[11];
    const float *BW2 = (const float*)d_in[12], *Bb2 = (const float*)d_in[13];
    const float *BW3 = (const float*)d_in[14], *Bb3 = (const float*)d_in[15];
    const float *BW4 = (const float*)d_in[16], *Bb4 = (const float*)d_in[17];
    float* out = (float*)d_out;

    const long WS = (long)DMID * DMID;   // per-domain weight stride (branch layers)

    setup_kernel<<<1, 1024>>>(dom);
    build_perm_kernel<<<(BB + 255) / 256, 256>>>(dom);

    dim3 grid(NTILES, MTILES);
    // layer 1: gather X -> bufA
    gemm128_kernel<true ><<<grid, 256>>>(X,       0, W1,  b1,  0, DIN,  0,  0,    1);
    // shared layers
    gemm128_kernel<false><<<grid, 256>>>(nullptr, 0, W2,  b2,  1, DMID, 0,  0,    1);
    gemm128_kernel<false><<<grid, 256>>>(nullptr, 1, W3,  b3,  0, DMID, 0,  0,    1);
    gemm128_kernel<false><<<grid, 256>>>(nullptr, 0, W4,  b4,  1, DMID, 0,  0,    1);
    // routed branch layers (per-tile domain via padded segments)
    gemm128_kernel<false><<<grid, 256>>>(nullptr, 1, BW1, Bb1, 0, DMID, WS, DMID, 1);
    gemm128_kernel<false><<<grid, 256>>>(nullptr, 0, BW2, Bb2, 1, DMID, WS, DMID, 1);
    gemm128_kernel<false><<<grid, 256>>>(nullptr, 1, BW3, Bb3, 0, DMID, WS, DMID, 1);
    // final layer + scatter
    gemm_last_kernel<<<MTILES, 256>>>(0, BW4, Bb4, out);
}